// round 12
// baseline (speedup 1.0000x reference)
#include <cuda_runtime.h>
#include <math.h>

#define NC 64
#define NF 128
#define NS 192
#define RPB 8        // rays per block, 1 warp each

// skewed index for stw (kills stride-6 bank conflicts)
#define SK(s) ((s) + ((s) >> 4))

// compare-exchange a pair of registers; 'up' => a gets min
#define CEPAIR(a, b, up) { float _mn = fminf(a, b), _mx = fmaxf(a, b); \
                           a = (up) ? _mn : _mx; b = (up) ? _mx : _mn; }

// rank of c in sorted su[0..127] (strict <, pads [128..191] = +inf)
#define RANK128(res, su, c) {                       \
    int _r = 0;                                     \
    if ((su)[127]      < (c)) _r = 128;             \
    if ((su)[_r + 63]  < (c)) _r += 64;             \
    if ((su)[_r + 31]  < (c)) _r += 32;             \
    if ((su)[_r + 15]  < (c)) _r += 16;             \
    if ((su)[_r + 7]   < (c)) _r += 8;              \
    if ((su)[_r + 3]   < (c)) _r += 4;              \
    if ((su)[_r + 1]   < (c)) _r += 2;              \
    if ((su)[_r]       < (c)) _r += 1;              \
    (res) = _r; }

__global__ __launch_bounds__(256, 5) void gridnerf_kernel(
    const float* __restrict__ ro,      // [N,3]
    const float* __restrict__ rd,      // [N,3]
    const float* __restrict__ cw,      // [N,NC]
    const float* __restrict__ ct,      // [N,NC]
    const float* __restrict__ uu_in,   // [N,NF]
    const float* __restrict__ colors,  // [N,NS,3]
    const float* __restrict__ dens,    // [N,NS]
    float* __restrict__ out_rgb,       // [N,3]
    float* __restrict__ out_depth,     // [N]
    float* __restrict__ out_op,        // [N]
    float* __restrict__ out_fp,        // [N,NS,3]
    int nrays)
{
    const int L   = threadIdx.x & 31;
    const int w   = threadIdx.x >> 5;
    const int ray = blockIdx.x * RPB + w;
    if (ray >= nrays) return;          // warp-uniform exit; no block barriers used

    __shared__ float2 sh_cc[RPB][64];   // (cdf[i], ct[i])
    __shared__ float  sh_u [RPB][192];  // sorted u, pads +inf
    __shared__ int    sh_mk[RPB][160];  // boundary-rank histogram
    __shared__ float  sh_t [RPB][192];  // merged sorted t
    __shared__ float2 sh_tw[RPB][204];  // (t, weight), skewed

    float2* cc  = sh_cc[w];
    float*  su  = sh_u[w];
    int*    mk  = sh_mk[w];
    float*  st  = sh_t[w];
    float2* stw = sh_tw[w];

    // ---- A: global loads (coalesced / vectorized) ----
    const float4 u4 = ((const float4*)(uu_in + (size_t)ray * NF))[L];
    float v0 = u4.x, v1 = u4.y, v2 = u4.z, v3 = u4.w;   // elements 4L..4L+3

    const float2 cw2 = ((const float2*)(cw + (size_t)ray * NC))[L];
    const float2 ct2 = ((const float2*)(ct + (size_t)ray * NC))[L];

    // ro/rd: one predicated lane-load + shfl broadcasts
    float odv = 0.f;
    if (L < 6) {
        const float* p = (L < 3) ? (ro + 3 * ray + L) : (rd + 3 * ray + L - 3);
        odv = *p;
    }
    const float ox = __shfl_sync(0xffffffffu, odv, 0);
    const float oy = __shfl_sync(0xffffffffu, odv, 1);
    const float oz = __shfl_sync(0xffffffffu, odv, 2);
    const float dx = __shfl_sync(0xffffffffu, odv, 3);
    const float dy = __shfl_sync(0xffffffffu, odv, 4);
    const float dz = __shfl_sync(0xffffffffu, odv, 5);
    const float dnorm = sqrtf(dx * dx + dy * dy + dz * dz);

    // ---- B: cdf build (pair-per-lane warp scan); boundaries stay in regs ----
    float cdf_b1, cdf_b2;               // cdf[2L+1], cdf[2L+2]
    {
        const float a  = cw2.x + 1e-5f;
        const float b  = cw2.y + 1e-5f;
        const float ps = a + b;
        float inc = ps;
        #pragma unroll
        for (int off = 1; off < 32; off <<= 1) {
            float n = __shfl_up_sync(0xffffffffu, inc, off);
            if (L >= off) inc += n;
        }
        const float total = __shfl_sync(0xffffffffu, inc, 31);
        const float invt  = 1.f / total;
        const float excl  = inc - ps;
        const float cdf_e = excl * invt;          // cdf[2L]
        cdf_b1 = (excl + a)  * invt;              // cdf[2L+1]
        cdf_b2 = (excl + ps) * invt;              // cdf[2L+2]
        *(float4*)(cc + 2 * L) = make_float4(cdf_e, ct2.x, cdf_b1, ct2.y);
        su[128 + L] = 3.4e38f;
        su[160 + L] = 3.4e38f;
        mk[L]       = 0;
        mk[32 + L]  = 0;
        mk[64 + L]  = 0;
        mk[96 + L]  = 0;
        mk[128 + L] = 0;
    }

    // ---- C: bitonic sort of 128 u, 4 elements/thread (e = 4L+i) ----
    #pragma unroll
    for (int k = 2; k <= 128; k <<= 1) {
        #pragma unroll
        for (int j = k >> 1; j >= 4; j >>= 1) {
            const bool up = ((L & (k >> 2)) == 0);   // k>=8 here
            const bool lw = ((L & (j >> 2)) == 0);
            const bool km = (up == lw);
            float w0 = __shfl_xor_sync(0xffffffffu, v0, j >> 2);
            float w1 = __shfl_xor_sync(0xffffffffu, v1, j >> 2);
            float w2 = __shfl_xor_sync(0xffffffffu, v2, j >> 2);
            float w3 = __shfl_xor_sync(0xffffffffu, v3, j >> 2);
            v0 = km ? fminf(v0, w0) : fmaxf(v0, w0);
            v1 = km ? fminf(v1, w1) : fmaxf(v1, w1);
            v2 = km ? fminf(v2, w2) : fmaxf(v2, w2);
            v3 = km ? fminf(v3, w3) : fmaxf(v3, w3);
        }
        if (k >= 4) {  // j = 2 : pairs (v0,v2), (v1,v3)
            const bool up = (k == 4) ? ((L & 1) == 0) : ((L & (k >> 2)) == 0);
            CEPAIR(v0, v2, up); CEPAIR(v1, v3, up);
        }
        // j = 1 : pairs (v0,v1), (v2,v3)
        if (k == 2) {
            CEPAIR(v0, v1, true);  CEPAIR(v2, v3, false);
        } else {
            const bool up = (k == 4) ? ((L & 1) == 0) : ((L & (k >> 2)) == 0);
            CEPAIR(v0, v1, up);    CEPAIR(v2, v3, up);
        }
    }
    *(float4*)(su + 4 * L) = make_float4(v0, v1, v2, v3);
    __syncwarp();

    // ---- D1: boundary ranks in sorted u; histogram + coarse scatter ----
    {
        int s1, s2;
        RANK128(s1, su, cdf_b1);   // rank of cdf[2L+1]
        RANK128(s2, su, cdf_b2);   // rank of cdf[2L+2]
        atomicAdd(&mk[s1], 1);
        atomicAdd(&mk[s2], 1);
        int r0 = __shfl_up_sync(0xffffffffu, s2, 1);
        if (L == 0) r0 = 0;
        st[2 * L + r0]     = ct2.x;
        st[2 * L + 1 + s1] = ct2.y;
    }
    __syncwarp();

    // ---- D2: lo via prefix of histogram; interpolate + scatter fine ----
    {
        const int4 m4 = *(const int4*)(mk + 4 * L);
        const int c0 = m4.x;
        const int c1 = c0 + m4.y;
        const int c2 = c1 + m4.z;
        const int c3 = c2 + m4.w;
        int inc = c3;
        #pragma unroll
        for (int off = 1; off < 32; off <<= 1) {
            int n = __shfl_up_sync(0xffffffffu, inc, off);
            if (L >= off) inc += n;
        }
        const int exc = inc - c3;
        const int lov[4] = {1 + exc + c0, 1 + exc + c1, 1 + exc + c2, 1 + exc + c3};
        const float va[4] = {v0, v1, v2, v3};
        #pragma unroll
        for (int i = 0; i < 4; i++) {
            const int   lo = lov[i];
            const float uu = va[i];
            const int below = min(lo - 1, NC - 1);
            const int above = min(lo,     NC - 1);
            const float2 ccb = cc[below];
            const float2 cca = cc[above];
            float denom = cca.x - ccb.x;
            if (denom < 1e-5f) denom = 1.f;
            const float tt = (uu - ccb.x) / denom;
            const float fv = ccb.y + tt * (cca.y - ccb.y);
            st[4 * L + i + min(lo, NC)] = fv;
        }
    }
    __syncwarp();

    // ---- F: alpha + transmittance (thread owns samples 6L..6L+5) ----
    float dep = 0.f, op = 0.f;
    {
        const float2 tA = *(const float2*)(st + 6 * L);
        const float2 tB = *(const float2*)(st + 6 * L + 2);
        const float2 tC = *(const float2*)(st + 6 * L + 4);
        const float tb[6] = {tA.x, tA.y, tB.x, tB.y, tC.x, tC.y};
        const float t6 = (L < 31) ? st[6 * L + 6] : 0.f;

        const float* dvp = dens + (size_t)ray * NS + 6 * L;
        const float2 dva = *(const float2*)(dvp + 0);
        const float2 dvb = *(const float2*)(dvp + 2);
        const float2 dvc = *(const float2*)(dvp + 4);
        const float dvv[6] = {dva.x, dva.y, dvb.x, dvb.y, dvc.x, dvc.y};

        float alpha[6];
        float run = 1.f;
        #pragma unroll
        for (int i = 0; i < 6; i++) {
            float dist;
            if (i < 5)          dist = tb[i + 1] - tb[i];
            else if (L == 31)   dist = 1e10f;
            else                dist = t6 - tb[5];
            dist *= dnorm;
            alpha[i] = 1.f - __expf(-dvv[i] * dist);
            run *= (1.f - alpha[i] + 1e-10f);
        }
        float inc = run;
        #pragma unroll
        for (int off = 1; off < 32; off <<= 1) {
            float n = __shfl_up_sync(0xffffffffu, inc, off);
            if (L >= off) inc *= n;
        }
        float wex = __shfl_up_sync(0xffffffffu, inc, 1);
        if (L == 0) wex = 1.f;

        float run2 = wex;                 // running transmittance
        #pragma unroll
        for (int i = 0; i < 6; i++) {
            const float wt = alpha[i] * run2;
            const int s = 6 * L + i;
            stw[SK(s)] = make_float2(tb[i], wt);
            dep += wt * tb[i];
            op  += wt;
            run2 *= (1.f - alpha[i] + 1e-10f);
        }
    }
    __syncwarp();

    // ---- G: float4 fp stores + rgb accumulation ----
    // rotated accumulators: AR[q] == channel (rB + q) % 3
    float A0 = 0.f, A1 = 0.f, A2 = 0.f;
    const int rB = L % 3;
    {
        const float oR0 = (rB == 0) ? ox : ((rB == 1) ? oy : oz);
        const float oR1 = (rB == 0) ? oy : ((rB == 1) ? oz : ox);
        const float oR2 = (rB == 0) ? oz : ((rB == 1) ? ox : oy);
        const float dR0 = (rB == 0) ? dx : ((rB == 1) ? dy : dz);
        const float dR1 = (rB == 0) ? dy : ((rB == 1) ? dz : dx);
        const float dR2 = (rB == 0) ? dz : ((rB == 1) ? dx : dy);
        float* fpb = out_fp + (size_t)ray * (NS * 3);
        const float4* c4 = (const float4*)(colors + (size_t)ray * (NS * 3));

        #pragma unroll
        for (int h = 0; h < 4; h++) {
            const float4 cvi = __ldg(&c4[32 * h + L]);
            const int e0  = 128 * h + 4 * L;
            const int sa  = e0 / 3;
            const int r0  = e0 - 3 * sa;           // e0 % 3 (runtime via rB)
            const float2 twa = stw[SK(sa)];
            const float2 twb = stw[SK(sa + 1)];
            // float j uses s_b iff r0 + j >= 3
            const float t0 = twa.x;
            const float w0 = twa.y;
            const float t1 = (r0 == 2) ? twb.x : twa.x;
            const float w1 = (r0 == 2) ? twb.y : twa.y;
            const float t2 = (r0 >= 1) ? twb.x : twa.x;
            const float w2 = (r0 >= 1) ? twb.y : twa.y;
            const float t3 = twb.x;
            const float w3 = twb.y;
            // channel slot q_j = (2h + j) % 3 (compile-time)
            const int q0 = (2 * h + 0) % 3, q1 = (2 * h + 1) % 3;
            const int q2 = (2 * h + 2) % 3, q3 = (2 * h + 3) % 3;
            const float oA = (q0 == 0) ? oR0 : ((q0 == 1) ? oR1 : oR2);
            const float dA = (q0 == 0) ? dR0 : ((q0 == 1) ? dR1 : dR2);
            const float oB = (q1 == 0) ? oR0 : ((q1 == 1) ? oR1 : oR2);
            const float dB = (q1 == 0) ? dR0 : ((q1 == 1) ? dR1 : dR2);
            const float oC = (q2 == 0) ? oR0 : ((q2 == 1) ? oR1 : oR2);
            const float dC = (q2 == 0) ? dR0 : ((q2 == 1) ? dR1 : dR2);
            const float oD = (q3 == 0) ? oR0 : ((q3 == 1) ? oR1 : oR2);
            const float dD = (q3 == 0) ? dR0 : ((q3 == 1) ? dR1 : dR2);
            *(float4*)(fpb + e0) = make_float4(oA + dA * t0, oB + dB * t1,
                                               oC + dC * t2, oD + dD * t3);
            const float g0 = w0 * cvi.x, g1 = w1 * cvi.y;
            const float g2 = w2 * cvi.z, g3 = w3 * cvi.w;
            if (q0 == 0) A0 += g0; else if (q0 == 1) A1 += g0; else A2 += g0;
            if (q1 == 0) A0 += g1; else if (q1 == 1) A1 += g1; else A2 += g1;
            if (q2 == 0) A0 += g2; else if (q2 == 1) A1 += g2; else A2 += g2;
            if (q3 == 0) A0 += g3; else if (q3 == 1) A1 += g3; else A2 += g3;
        }

        // tail: elements 512 + 2L, 512 + 2L + 1 (float2)
        {
            const float2* c2p = (const float2*)(colors + (size_t)ray * (NS * 3) + 512);
            const float2 cvi = __ldg(&c2p[L]);
            const int e0 = 512 + 2 * L;
            const int s0 = e0 / 3;
            const int s1 = (e0 + 1) / 3;
            const float2 tw0 = stw[SK(s0)];
            const float2 tw1 = stw[SK(s1)];
            // q_j = (2 + rB + j) % 3, runtime
            const int qt0 = (2 + rB) % 3;
            const int qt1 = rB;
            const float o0 = (qt0 == 0) ? oR0 : ((qt0 == 1) ? oR1 : oR2);
            const float d0 = (qt0 == 0) ? dR0 : ((qt0 == 1) ? dR1 : dR2);
            const float o1 = (qt1 == 0) ? oR0 : ((qt1 == 1) ? oR1 : oR2);
            const float d1 = (qt1 == 0) ? dR0 : ((qt1 == 1) ? dR1 : dR2);
            *(float2*)(fpb + e0) = make_float2(o0 + d0 * tw0.x, o1 + d1 * tw1.x);
            const float g0 = tw0.y * cvi.x;
            const float g1 = tw1.y * cvi.y;
            if (qt0 == 0) A0 += g0; else if (qt0 == 1) A1 += g0; else A2 += g0;
            if (qt1 == 0) A0 += g1; else if (qt1 == 1) A1 += g1; else A2 += g1;
        }
    }

    // ---- H: final reductions (single warp, no shared) ----
    {
        // channel c sum lives in AR[(c - rB) mod 3] == AR[(c + 2L) % 3]
        const int i0 = (2 * L) % 3, i1 = (2 * L + 1) % 3, i2 = (2 * L + 2) % 3;
        float rC = (i0 == 0) ? A0 : ((i0 == 1) ? A1 : A2);
        float gC = (i1 == 0) ? A0 : ((i1 == 1) ? A1 : A2);
        float bC = (i2 == 0) ? A0 : ((i2 == 1) ? A1 : A2);
        #pragma unroll
        for (int off = 16; off; off >>= 1) {
            rC  += __shfl_xor_sync(0xffffffffu, rC,  off);
            gC  += __shfl_xor_sync(0xffffffffu, gC,  off);
            bC  += __shfl_xor_sync(0xffffffffu, bC,  off);
            dep += __shfl_xor_sync(0xffffffffu, dep, off);
            op  += __shfl_xor_sync(0xffffffffu, op,  off);
        }
        if (L == 0) {
            out_rgb[3 * ray + 0] = rC;
            out_rgb[3 * ray + 1] = gC;
            out_rgb[3 * ray + 2] = bC;
            out_depth[ray] = dep;
            out_op[ray]    = op;
        }
    }
}

extern "C" void kernel_launch(void* const* d_in, const int* in_sizes, int n_in,
                              void* d_out, int out_size)
{
    const float* ro     = (const float*)d_in[0];
    const float* rd     = (const float*)d_in[1];
    const float* cw     = (const float*)d_in[2];
    const float* ct     = (const float*)d_in[3];
    const float* u      = (const float*)d_in[4];
    const float* colors = (const float*)d_in[5];
    const float* dens   = (const float*)d_in[6];

    const int N = in_sizes[0] / 3;

    float* out       = (float*)d_out;
    float* out_rgb   = out;                 // [N,3]
    float* out_depth = out + (size_t)N * 3; // [N]
    float* out_op    = out_depth + N;       // [N]
    float* out_fp    = out_op + N;          // [N,NS,3]

    const int blocks = (N + RPB - 1) / RPB;
    gridnerf_kernel<<<blocks, 32 * RPB>>>(ro, rd, cw, ct, u, colors, dens,
                                          out_rgb, out_depth, out_op, out_fp, N);
}

// round 13
// speedup vs baseline: 1.0046x; 1.0046x over previous
#include <cuda_runtime.h>
#include <math.h>

#define NC 64
#define NF 128
#define NS 192
#define RPB 8        // rays per block, 1 warp each

// skewed index for stw (kills stride-6 float2 bank conflicts)
#define SK(s) ((s) + ((s) >> 4))

// compare-exchange a pair of registers; 'up' => a gets min
#define CEPAIR(a, b, up) { float _mn = fminf(a, b), _mx = fmaxf(a, b); \
                           a = (up) ? _mn : _mx; b = (up) ? _mx : _mn; }

// rank of c in sorted su[0..127] (strict <, pads [128..191] = +inf)
#define RANK128(res, su, c) {                       \
    int _r = 0;                                     \
    if ((su)[127]      < (c)) _r = 128;             \
    if ((su)[_r + 63]  < (c)) _r += 64;             \
    if ((su)[_r + 31]  < (c)) _r += 32;             \
    if ((su)[_r + 15]  < (c)) _r += 16;             \
    if ((su)[_r + 7]   < (c)) _r += 8;              \
    if ((su)[_r + 3]   < (c)) _r += 4;              \
    if ((su)[_r + 1]   < (c)) _r += 2;              \
    if ((su)[_r]       < (c)) _r += 1;              \
    (res) = _r; }

__global__ __launch_bounds__(256, 5) void gridnerf_kernel(
    const float* __restrict__ ro,      // [N,3]
    const float* __restrict__ rd,      // [N,3]
    const float* __restrict__ cw,      // [N,NC]
    const float* __restrict__ ct,      // [N,NC]
    const float* __restrict__ uu_in,   // [N,NF]
    const float* __restrict__ colors,  // [N,NS,3]
    const float* __restrict__ dens,    // [N,NS]
    float* __restrict__ out_rgb,       // [N,3]
    float* __restrict__ out_depth,     // [N]
    float* __restrict__ out_op,        // [N]
    float* __restrict__ out_fp,        // [N,NS,3]
    int nrays)
{
    const int L   = threadIdx.x & 31;
    const int w   = threadIdx.x >> 5;
    const int ray = blockIdx.x * RPB + w;
    if (ray >= nrays) return;          // warp-uniform exit; no block barriers used

    __shared__ float2 sh_cc[RPB][64];   // (cdf[i], ct[i])
    __shared__ float  sh_u [RPB][192];  // sorted u, pads +inf
    __shared__ int    sh_mk[RPB][160];  // boundary-rank histogram
    __shared__ float  sh_t [RPB][192];  // merged sorted t
    __shared__ float2 sh_tw[RPB][204];  // (t, weight), skewed

    float2* cc  = sh_cc[w];
    float*  su  = sh_u[w];
    int*    mk  = sh_mk[w];
    float*  st  = sh_t[w];
    float2* stw = sh_tw[w];

    // ---- A: global loads (coalesced / vectorized) ----
    const float4 u4 = ((const float4*)(uu_in + (size_t)ray * NF))[L];
    float v0 = u4.x, v1 = u4.y, v2 = u4.z, v3 = u4.w;   // elements 4L..4L+3

    const float2 cw2 = ((const float2*)(cw + (size_t)ray * NC))[L];
    const float2 ct2 = ((const float2*)(ct + (size_t)ray * NC))[L];

    // ro/rd: one predicated lane-load + shfl broadcasts
    float odv = 0.f;
    if (L < 6) {
        const float* p = (L < 3) ? (ro + 3 * ray + L) : (rd + 3 * ray + L - 3);
        odv = *p;
    }
    const float ox = __shfl_sync(0xffffffffu, odv, 0);
    const float oy = __shfl_sync(0xffffffffu, odv, 1);
    const float oz = __shfl_sync(0xffffffffu, odv, 2);
    const float dx = __shfl_sync(0xffffffffu, odv, 3);
    const float dy = __shfl_sync(0xffffffffu, odv, 4);
    const float dz = __shfl_sync(0xffffffffu, odv, 5);
    const float dnorm = sqrtf(dx * dx + dy * dy + dz * dz);

    // ---- B: cdf build (pair-per-lane warp scan); boundaries stay in regs ----
    float cdf_b1, cdf_b2;               // cdf[2L+1], cdf[2L+2]
    {
        const float a  = cw2.x + 1e-5f;
        const float b  = cw2.y + 1e-5f;
        const float ps = a + b;
        float inc = ps;
        #pragma unroll
        for (int off = 1; off < 32; off <<= 1) {
            float n = __shfl_up_sync(0xffffffffu, inc, off);
            if (L >= off) inc += n;
        }
        const float total = __shfl_sync(0xffffffffu, inc, 31);
        const float invt  = 1.f / total;
        const float excl  = inc - ps;
        const float cdf_e = excl * invt;          // cdf[2L]
        cdf_b1 = (excl + a)  * invt;              // cdf[2L+1]
        cdf_b2 = (excl + ps) * invt;              // cdf[2L+2]
        *(float4*)(cc + 2 * L) = make_float4(cdf_e, ct2.x, cdf_b1, ct2.y);
        su[128 + L] = 3.4e38f;
        su[160 + L] = 3.4e38f;
        mk[L]       = 0;
        mk[32 + L]  = 0;
        mk[64 + L]  = 0;
        mk[96 + L]  = 0;
        mk[128 + L] = 0;
    }

    // ---- C: bitonic sort of 128 u, 4 elements/thread (e = 4L+i) ----
    #pragma unroll
    for (int k = 2; k <= 128; k <<= 1) {
        #pragma unroll
        for (int j = k >> 1; j >= 4; j >>= 1) {
            const bool up = ((L & (k >> 2)) == 0);   // k>=8 here
            const bool lw = ((L & (j >> 2)) == 0);
            const bool km = (up == lw);
            float w0 = __shfl_xor_sync(0xffffffffu, v0, j >> 2);
            float w1 = __shfl_xor_sync(0xffffffffu, v1, j >> 2);
            float w2 = __shfl_xor_sync(0xffffffffu, v2, j >> 2);
            float w3 = __shfl_xor_sync(0xffffffffu, v3, j >> 2);
            v0 = km ? fminf(v0, w0) : fmaxf(v0, w0);
            v1 = km ? fminf(v1, w1) : fmaxf(v1, w1);
            v2 = km ? fminf(v2, w2) : fmaxf(v2, w2);
            v3 = km ? fminf(v3, w3) : fmaxf(v3, w3);
        }
        if (k >= 4) {  // j = 2 : pairs (v0,v2), (v1,v3)
            const bool up = (k == 4) ? ((L & 1) == 0) : ((L & (k >> 2)) == 0);
            CEPAIR(v0, v2, up); CEPAIR(v1, v3, up);
        }
        // j = 1 : pairs (v0,v1), (v2,v3)
        if (k == 2) {
            CEPAIR(v0, v1, true);  CEPAIR(v2, v3, false);
        } else {
            const bool up = (k == 4) ? ((L & 1) == 0) : ((L & (k >> 2)) == 0);
            CEPAIR(v0, v1, up);    CEPAIR(v2, v3, up);
        }
    }
    *(float4*)(su + 4 * L) = make_float4(v0, v1, v2, v3);
    __syncwarp();

    // ---- D1: boundary ranks in sorted u; histogram + coarse scatter ----
    {
        int s1, s2;
        RANK128(s1, su, cdf_b1);   // rank of cdf[2L+1]
        RANK128(s2, su, cdf_b2);   // rank of cdf[2L+2]
        atomicAdd(&mk[s1], 1);
        atomicAdd(&mk[s2], 1);
        int r0 = __shfl_up_sync(0xffffffffu, s2, 1);
        if (L == 0) r0 = 0;
        st[2 * L + r0]     = ct2.x;
        st[2 * L + 1 + s1] = ct2.y;
    }
    __syncwarp();

    // ---- D2: lo via prefix of histogram; interpolate + scatter fine ----
    {
        const int4 m4 = *(const int4*)(mk + 4 * L);
        const int c0 = m4.x;
        const int c1 = c0 + m4.y;
        const int c2 = c1 + m4.z;
        const int c3 = c2 + m4.w;
        int inc = c3;
        #pragma unroll
        for (int off = 1; off < 32; off <<= 1) {
            int n = __shfl_up_sync(0xffffffffu, inc, off);
            if (L >= off) inc += n;
        }
        const int exc = inc - c3;
        const int lov[4] = {1 + exc + c0, 1 + exc + c1, 1 + exc + c2, 1 + exc + c3};
        const float va[4] = {v0, v1, v2, v3};
        #pragma unroll
        for (int i = 0; i < 4; i++) {
            const int   lo = lov[i];
            const float uu = va[i];
            const int below = min(lo - 1, NC - 1);
            const int above = min(lo,     NC - 1);
            const float2 ccb = cc[below];
            const float2 cca = cc[above];
            float denom = cca.x - ccb.x;
            if (denom < 1e-5f) denom = 1.f;
            const float tt = (uu - ccb.x) / denom;
            const float fv = ccb.y + tt * (cca.y - ccb.y);
            st[4 * L + i + min(lo, NC)] = fv;
        }
    }
    __syncwarp();

    // ---- F: alpha + transmittance (thread owns samples 6L..6L+5) ----
    float dep = 0.f, op = 0.f;
    {
        const float2 tA = *(const float2*)(st + 6 * L);
        const float2 tB = *(const float2*)(st + 6 * L + 2);
        const float2 tC = *(const float2*)(st + 6 * L + 4);
        const float tb[6] = {tA.x, tA.y, tB.x, tB.y, tC.x, tC.y};
        const float t6 = (L < 31) ? st[6 * L + 6] : 0.f;

        const float* dvp = dens + (size_t)ray * NS + 6 * L;
        const float2 dva = *(const float2*)(dvp + 0);
        const float2 dvb = *(const float2*)(dvp + 2);
        const float2 dvc = *(const float2*)(dvp + 4);
        const float dvv[6] = {dva.x, dva.y, dvb.x, dvb.y, dvc.x, dvc.y};

        float alpha[6];
        float run = 1.f;
        #pragma unroll
        for (int i = 0; i < 6; i++) {
            float dist;
            if (i < 5)          dist = tb[i + 1] - tb[i];
            else if (L == 31)   dist = 1e10f;
            else                dist = t6 - tb[5];
            dist *= dnorm;
            alpha[i] = 1.f - __expf(-dvv[i] * dist);
            run *= (1.f - alpha[i] + 1e-10f);
        }
        float inc = run;
        #pragma unroll
        for (int off = 1; off < 32; off <<= 1) {
            float n = __shfl_up_sync(0xffffffffu, inc, off);
            if (L >= off) inc *= n;
        }
        float wex = __shfl_up_sync(0xffffffffu, inc, 1);
        if (L == 0) wex = 1.f;

        float run2 = wex;                 // running transmittance
        #pragma unroll
        for (int i = 0; i < 6; i++) {
            const float wt = alpha[i] * run2;
            const int s = 6 * L + i;
            stw[SK(s)] = make_float2(tb[i], wt);
            dep += wt * tb[i];
            op  += wt;
            run2 *= (1.f - alpha[i] + 1e-10f);
        }
    }
    __syncwarp();

    // ---- G: fused coalesced fp stores + rgb accumulation (R10 form + SK) ----
    float A0 = 0.f, A1 = 0.f, A2 = 0.f;
    {
        const int rho = (2 * L) % 3;
        const float oR0 = (rho == 0) ? ox : ((rho == 1) ? oy : oz);
        const float oR1 = (rho == 0) ? oy : ((rho == 1) ? oz : ox);
        const float oR2 = (rho == 0) ? oz : ((rho == 1) ? ox : oy);
        const float dR0 = (rho == 0) ? dx : ((rho == 1) ? dy : dz);
        const float dR1 = (rho == 0) ? dy : ((rho == 1) ? dz : dx);
        const float dR2 = (rho == 0) ? dz : ((rho == 1) ? dx : dy);
        float* fpb = out_fp + (size_t)ray * (NS * 3);
        const float2* c2 = (const float2*)(colors + (size_t)ray * (NS * 3));

        #pragma unroll
        for (int i = 0; i < 9; i++) {
            const float2 cvi = __ldg(&c2[32 * i + L]);
            const int e0  = 64 * i + 2 * L;
            const int s0  = e0 / 3;
            const int c0r = e0 - 3 * s0;
            const int s1  = s0 + (c0r == 2 ? 1 : 0);
            const float2 tw0 = stw[SK(s0)];
            const float2 tw1 = stw[SK(s1)];
            const int q0 = i % 3, q1 = (i + 1) % 3;   // compile-time slots
            const float o0 = (q0 == 0) ? oR0 : ((q0 == 1) ? oR1 : oR2);
            const float d0 = (q0 == 0) ? dR0 : ((q0 == 1) ? dR1 : dR2);
            const float o1 = (q1 == 0) ? oR0 : ((q1 == 1) ? oR1 : oR2);
            const float d1 = (q1 == 0) ? dR0 : ((q1 == 1) ? dR1 : dR2);
            *(float2*)(fpb + e0) = make_float2(o0 + d0 * tw0.x, o1 + d1 * tw1.x);
            const float g0 = tw0.y * cvi.x;
            const float g1 = tw1.y * cvi.y;
            if (q0 == 0) A0 += g0; else if (q0 == 1) A1 += g0; else A2 += g0;
            if (q1 == 0) A0 += g1; else if (q1 == 1) A1 += g1; else A2 += g1;
        }
    }

    // ---- H: final reductions (single warp, no shared) ----
    {
        const int i0 = (0 + L) % 3, i1 = (1 + L) % 3, i2 = (2 + L) % 3;
        float rC = (i0 == 0) ? A0 : ((i0 == 1) ? A1 : A2);
        float gC = (i1 == 0) ? A0 : ((i1 == 1) ? A1 : A2);
        float bC = (i2 == 0) ? A0 : ((i2 == 1) ? A1 : A2);
        #pragma unroll
        for (int off = 16; off; off >>= 1) {
            rC  += __shfl_xor_sync(0xffffffffu, rC,  off);
            gC  += __shfl_xor_sync(0xffffffffu, gC,  off);
            bC  += __shfl_xor_sync(0xffffffffu, bC,  off);
            dep += __shfl_xor_sync(0xffffffffu, dep, off);
            op  += __shfl_xor_sync(0xffffffffu, op,  off);
        }
        if (L == 0) {
            out_rgb[3 * ray + 0] = rC;
            out_rgb[3 * ray + 1] = gC;
            out_rgb[3 * ray + 2] = bC;
            out_depth[ray] = dep;
            out_op[ray]    = op;
        }
    }
}

extern "C" void kernel_launch(void* const* d_in, const int* in_sizes, int n_in,
                              void* d_out, int out_size)
{
    const float* ro     = (const float*)d_in[0];
    const float* rd     = (const float*)d_in[1];
    const float* cw     = (const float*)d_in[2];
    const float* ct     = (const float*)d_in[3];
    const float* u      = (const float*)d_in[4];
    const float* colors = (const float*)d_in[5];
    const float* dens   = (const float*)d_in[6];

    const int N = in_sizes[0] / 3;

    float* out       = (float*)d_out;
    float* out_rgb   = out;                 // [N,3]
    float* out_depth = out + (size_t)N * 3; // [N]
    float* out_op    = out_depth + N;       // [N]
    float* out_fp    = out_op + N;          // [N,NS,3]

    const int blocks = (N + RPB - 1) / RPB;
    gridnerf_kernel<<<blocks, 32 * RPB>>>(ro, rd, cw, ct, u, colors, dens,
                                          out_rgb, out_depth, out_op, out_fp, N);
}

// round 14
// speedup vs baseline: 1.0457x; 1.0410x over previous
#include <cuda_runtime.h>
#include <math.h>

#define NC 64
#define NF 128
#define NS 192
#define RPB 8        // rays per block, 1 warp each

// compare-exchange a pair of registers; 'up' => a gets min
#define CEPAIR(a, b, up) { float _mn = fminf(a, b), _mx = fmaxf(a, b); \
                           a = (up) ? _mn : _mx; b = (up) ? _mx : _mn; }

// rank of c in sorted su[0..127] (strict <, pads [128..191] = +inf)
#define RANK128(res, su, c) {                       \
    int _r = 0;                                     \
    if ((su)[127]      < (c)) _r = 128;             \
    if ((su)[_r + 63]  < (c)) _r += 64;             \
    if ((su)[_r + 31]  < (c)) _r += 32;             \
    if ((su)[_r + 15]  < (c)) _r += 16;             \
    if ((su)[_r + 7]   < (c)) _r += 8;              \
    if ((su)[_r + 3]   < (c)) _r += 4;              \
    if ((su)[_r + 1]   < (c)) _r += 2;              \
    if ((su)[_r]       < (c)) _r += 1;              \
    (res) = _r; }

__global__ __launch_bounds__(256, 5) void gridnerf_kernel(
    const float* __restrict__ ro,      // [N,3]
    const float* __restrict__ rd,      // [N,3]
    const float* __restrict__ cw,      // [N,NC]
    const float* __restrict__ ct,      // [N,NC]
    const float* __restrict__ uu_in,   // [N,NF]
    const float* __restrict__ colors,  // [N,NS,3]
    const float* __restrict__ dens,    // [N,NS]
    float* __restrict__ out_rgb,       // [N,3]
    float* __restrict__ out_depth,     // [N]
    float* __restrict__ out_op,        // [N]
    float* __restrict__ out_fp,        // [N,NS,3]
    int nrays)
{
    const int L   = threadIdx.x & 31;
    const int w   = threadIdx.x >> 5;
    const int ray = blockIdx.x * RPB + w;
    if (ray >= nrays) return;          // warp-uniform exit; no block barriers used

    __shared__ float2 sh_cc[RPB][64];   // (cdf[i], ct[i])
    __shared__ float  sh_u [RPB][192];  // sorted u, pads +inf
    __shared__ int    sh_mk[RPB][160];  // boundary-rank histogram
    __shared__ float  sh_t [RPB][192];  // merged sorted t
    __shared__ float2 sh_tw[RPB][192];  // (t, weight), plain layout

    float2* cc  = sh_cc[w];
    float*  su  = sh_u[w];
    int*    mk  = sh_mk[w];
    float*  st  = sh_t[w];
    float2* stw = sh_tw[w];

    // ---- A: global loads (coalesced / vectorized) ----
    const float4 u4 = ((const float4*)(uu_in + (size_t)ray * NF))[L];
    float v0 = u4.x, v1 = u4.y, v2 = u4.z, v3 = u4.w;   // elements 4L..4L+3

    const float2 cw2 = ((const float2*)(cw + (size_t)ray * NC))[L];
    const float2 ct2 = ((const float2*)(ct + (size_t)ray * NC))[L];

    const float ox = ro[3 * ray + 0], oy = ro[3 * ray + 1], oz = ro[3 * ray + 2];
    const float dx = rd[3 * ray + 0], dy = rd[3 * ray + 1], dz = rd[3 * ray + 2];
    const float dnorm = sqrtf(dx * dx + dy * dy + dz * dz);

    // ---- B: cdf build (pair-per-lane warp scan); boundaries stay in regs ----
    float cdf_b1, cdf_b2;               // cdf[2L+1], cdf[2L+2]
    {
        const float a  = cw2.x + 1e-5f;
        const float b  = cw2.y + 1e-5f;
        const float ps = a + b;
        float inc = ps;
        #pragma unroll
        for (int off = 1; off < 32; off <<= 1) {
            float n = __shfl_up_sync(0xffffffffu, inc, off);
            if (L >= off) inc += n;
        }
        const float total = __shfl_sync(0xffffffffu, inc, 31);
        const float invt  = 1.f / total;
        const float excl  = inc - ps;
        const float cdf_e = excl * invt;          // cdf[2L]
        cdf_b1 = (excl + a)  * invt;              // cdf[2L+1]
        cdf_b2 = (excl + ps) * invt;              // cdf[2L+2]
        *(float4*)(cc + 2 * L) = make_float4(cdf_e, ct2.x, cdf_b1, ct2.y);
        su[128 + L] = 3.4e38f;
        su[160 + L] = 3.4e38f;
        mk[L]       = 0;
        mk[32 + L]  = 0;
        mk[64 + L]  = 0;
        mk[96 + L]  = 0;
        mk[128 + L] = 0;
    }

    // ---- C: bitonic sort of 128 u, 4 elements/thread (e = 4L+i) ----
    #pragma unroll
    for (int k = 2; k <= 128; k <<= 1) {
        #pragma unroll
        for (int j = k >> 1; j >= 4; j >>= 1) {
            const bool up = ((L & (k >> 2)) == 0);   // k>=8 here
            const bool lw = ((L & (j >> 2)) == 0);
            const bool km = (up == lw);
            float w0 = __shfl_xor_sync(0xffffffffu, v0, j >> 2);
            float w1 = __shfl_xor_sync(0xffffffffu, v1, j >> 2);
            float w2 = __shfl_xor_sync(0xffffffffu, v2, j >> 2);
            float w3 = __shfl_xor_sync(0xffffffffu, v3, j >> 2);
            v0 = km ? fminf(v0, w0) : fmaxf(v0, w0);
            v1 = km ? fminf(v1, w1) : fmaxf(v1, w1);
            v2 = km ? fminf(v2, w2) : fmaxf(v2, w2);
            v3 = km ? fminf(v3, w3) : fmaxf(v3, w3);
        }
        if (k >= 4) {  // j = 2 : pairs (v0,v2), (v1,v3)
            const bool up = (k == 4) ? ((L & 1) == 0) : ((L & (k >> 2)) == 0);
            CEPAIR(v0, v2, up); CEPAIR(v1, v3, up);
        }
        // j = 1 : pairs (v0,v1), (v2,v3)
        if (k == 2) {
            CEPAIR(v0, v1, true);  CEPAIR(v2, v3, false);
        } else {
            const bool up = (k == 4) ? ((L & 1) == 0) : ((L & (k >> 2)) == 0);
            CEPAIR(v0, v1, up);    CEPAIR(v2, v3, up);
        }
    }
    *(float4*)(su + 4 * L) = make_float4(v0, v1, v2, v3);
    __syncwarp();

    // ---- D1: boundary ranks in sorted u; histogram + coarse scatter ----
    {
        int s1, s2;
        RANK128(s1, su, cdf_b1);   // rank of cdf[2L+1]
        RANK128(s2, su, cdf_b2);   // rank of cdf[2L+2]
        atomicAdd(&mk[s1], 1);
        atomicAdd(&mk[s2], 1);
        int r0 = __shfl_up_sync(0xffffffffu, s2, 1);
        if (L == 0) r0 = 0;
        st[2 * L + r0]     = ct2.x;
        st[2 * L + 1 + s1] = ct2.y;
    }
    __syncwarp();

    // ---- D2: lo via prefix of histogram; interpolate + scatter fine ----
    {
        const int4 m4 = *(const int4*)(mk + 4 * L);
        const int c0 = m4.x;
        const int c1 = c0 + m4.y;
        const int c2 = c1 + m4.z;
        const int c3 = c2 + m4.w;
        int inc = c3;
        #pragma unroll
        for (int off = 1; off < 32; off <<= 1) {
            int n = __shfl_up_sync(0xffffffffu, inc, off);
            if (L >= off) inc += n;
        }
        const int exc = inc - c3;
        const int lov[4] = {1 + exc + c0, 1 + exc + c1, 1 + exc + c2, 1 + exc + c3};
        const float va[4] = {v0, v1, v2, v3};
        #pragma unroll
        for (int i = 0; i < 4; i++) {
            const int   lo = lov[i];
            const float uu = va[i];
            const int below = min(lo - 1, NC - 1);
            const int above = min(lo,     NC - 1);
            const float2 ccb = cc[below];
            const float2 cca = cc[above];
            float denom = cca.x - ccb.x;
            if (denom < 1e-5f) denom = 1.f;
            const float tt = (uu - ccb.x) / denom;
            const float fv = ccb.y + tt * (cca.y - ccb.y);
            st[4 * L + i + min(lo, NC)] = fv;
        }
    }
    __syncwarp();

    // ---- F: alpha + transmittance, PAIR-BLOCKED: thread owns samples
    //      {64c+2L, 64c+2L+1} for c = 0..2 (all coalesced accesses) ----
    float dep = 0.f, op = 0.f;
    {
        // coalesced t + density loads (one 8B op per group each)
        float ta[3], tb[3], da[3], db[3];
        #pragma unroll
        for (int c = 0; c < 3; c++) {
            const float2 tp = *(const float2*)(st + 64 * c + 2 * L);
            ta[c] = tp.x; tb[c] = tp.y;
            const float2 dp = *(const float2*)(dens + (size_t)ray * NS + 64 * c + 2 * L);
            da[c] = dp.x; db[c] = dp.y;
        }
        // neighbor t (start of next pair): shfl_down; lane 31 takes next group's lane 0
        float tn[3];
        #pragma unroll
        for (int c = 0; c < 3; c++)
            tn[c] = __shfl_down_sync(0xffffffffu, ta[c], 1);
        const float nx1 = __shfl_sync(0xffffffffu, ta[1], 0);
        const float nx2 = __shfl_sync(0xffffffffu, ta[2], 0);
        if (L == 31) { tn[0] = nx1; tn[1] = nx2; }

        float a0[3], a1[3], q[3];
        #pragma unroll
        for (int c = 0; c < 3; c++) {
            const float dist0 = (tb[c] - ta[c]) * dnorm;
            float dist1;
            if (c == 2 && L == 31) dist1 = 1e10f * dnorm;
            else                   dist1 = (tn[c] - tb[c]) * dnorm;
            a0[c] = 1.f - __expf(-da[c] * dist0);
            a1[c] = 1.f - __expf(-db[c] * dist1);
            q[c]  = (1.f - a0[c] + 1e-10f) * (1.f - a1[c] + 1e-10f);
        }

        // per-group exclusive scans (multiplicative) + group chaining
        float Tbase = 1.f;   // product of totals of previous groups
        #pragma unroll
        for (int c = 0; c < 3; c++) {
            float inc = q[c];
            #pragma unroll
            for (int off = 1; off < 32; off <<= 1) {
                float n = __shfl_up_sync(0xffffffffu, inc, off);
                if (L >= off) inc *= n;
            }
            float exc = __shfl_up_sync(0xffffffffu, inc, 1);
            if (L == 0) exc = 1.f;
            const float Gtot = __shfl_sync(0xffffffffu, inc, 31);

            const float T0 = Tbase * exc;                       // T at 64c+2L
            const float w0 = a0[c] * T0;
            const float w1 = a1[c] * T0 * (1.f - a0[c] + 1e-10f);
            *(float4*)(stw + 64 * c + 2 * L) = make_float4(ta[c], w0, tb[c], w1);
            dep += w0 * ta[c] + w1 * tb[c];
            op  += w0 + w1;
            Tbase *= Gtot;
        }
    }
    __syncwarp();

    // ---- G: fused coalesced fp stores + rgb accumulation (R10 form) ----
    float A0 = 0.f, A1 = 0.f, A2 = 0.f;
    {
        const int rho = (2 * L) % 3;
        const float oR0 = (rho == 0) ? ox : ((rho == 1) ? oy : oz);
        const float oR1 = (rho == 0) ? oy : ((rho == 1) ? oz : ox);
        const float oR2 = (rho == 0) ? oz : ((rho == 1) ? ox : oy);
        const float dR0 = (rho == 0) ? dx : ((rho == 1) ? dy : dz);
        const float dR1 = (rho == 0) ? dy : ((rho == 1) ? dz : dx);
        const float dR2 = (rho == 0) ? dz : ((rho == 1) ? dx : dy);
        float* fpb = out_fp + (size_t)ray * (NS * 3);
        const float2* c2 = (const float2*)(colors + (size_t)ray * (NS * 3));

        #pragma unroll
        for (int i = 0; i < 9; i++) {
            const float2 cvi = __ldg(&c2[32 * i + L]);
            const int e0  = 64 * i + 2 * L;
            const int s0  = e0 / 3;
            const int c0r = e0 - 3 * s0;
            const int s1  = s0 + (c0r == 2 ? 1 : 0);
            const float2 tw0 = stw[s0];
            const float2 tw1 = stw[s1];
            const int q0 = i % 3, q1 = (i + 1) % 3;   // compile-time slots
            const float o0 = (q0 == 0) ? oR0 : ((q0 == 1) ? oR1 : oR2);
            const float d0 = (q0 == 0) ? dR0 : ((q0 == 1) ? dR1 : dR2);
            const float o1 = (q1 == 0) ? oR0 : ((q1 == 1) ? oR1 : oR2);
            const float d1 = (q1 == 0) ? dR0 : ((q1 == 1) ? dR1 : dR2);
            *(float2*)(fpb + e0) = make_float2(o0 + d0 * tw0.x, o1 + d1 * tw1.x);
            const float g0 = tw0.y * cvi.x;
            const float g1 = tw1.y * cvi.y;
            if (q0 == 0) A0 += g0; else if (q0 == 1) A1 += g0; else A2 += g0;
            if (q1 == 0) A0 += g1; else if (q1 == 1) A1 += g1; else A2 += g1;
        }
    }

    // ---- H: final reductions (single warp, no shared) ----
    {
        const int i0 = (0 + L) % 3, i1 = (1 + L) % 3, i2 = (2 + L) % 3;
        float rC = (i0 == 0) ? A0 : ((i0 == 1) ? A1 : A2);
        float gC = (i1 == 0) ? A0 : ((i1 == 1) ? A1 : A2);
        float bC = (i2 == 0) ? A0 : ((i2 == 1) ? A1 : A2);
        #pragma unroll
        for (int off = 16; off; off >>= 1) {
            rC  += __shfl_xor_sync(0xffffffffu, rC,  off);
            gC  += __shfl_xor_sync(0xffffffffu, gC,  off);
            bC  += __shfl_xor_sync(0xffffffffu, bC,  off);
            dep += __shfl_xor_sync(0xffffffffu, dep, off);
            op  += __shfl_xor_sync(0xffffffffu, op,  off);
        }
        if (L == 0) {
            out_rgb[3 * ray + 0] = rC;
            out_rgb[3 * ray + 1] = gC;
            out_rgb[3 * ray + 2] = bC;
            out_depth[ray] = dep;
            out_op[ray]    = op;
        }
    }
}

extern "C" void kernel_launch(void* const* d_in, const int* in_sizes, int n_in,
                              void* d_out, int out_size)
{
    const float* ro     = (const float*)d_in[0];
    const float* rd     = (const float*)d_in[1];
    const float* cw     = (const float*)d_in[2];
    const float* ct     = (const float*)d_in[3];
    const float* u      = (const float*)d_in[4];
    const float* colors = (const float*)d_in[5];
    const float* dens   = (const float*)d_in[6];

    const int N = in_sizes[0] / 3;

    float* out       = (float*)d_out;
    float* out_rgb   = out;                 // [N,3]
    float* out_depth = out + (size_t)N * 3; // [N]
    float* out_op    = out_depth + N;       // [N]
    float* out_fp    = out_op + N;          // [N,NS,3]

    const int blocks = (N + RPB - 1) / RPB;
    gridnerf_kernel<<<blocks, 32 * RPB>>>(ro, rd, cw, ct, u, colors, dens,
                                          out_rgb, out_depth, out_op, out_fp, N);
}

// round 15
// speedup vs baseline: 1.0958x; 1.0479x over previous
#include <cuda_runtime.h>
#include <math.h>

#define NC 64
#define NF 128
#define NS 192
#define RPB 8        // rays per block, 1 warp each
#define FULLM 0xffffffffu

// compare-exchange a pair of registers; 'up' => a gets min
#define CEPAIR(a, b, up) { float _mn = fminf(a, b), _mx = fmaxf(a, b); \
                           a = (up) ? _mn : _mx; b = (up) ? _mx : _mn; }

__global__ __launch_bounds__(256, 5) void gridnerf_kernel(
    const float* __restrict__ ro,      // [N,3]
    const float* __restrict__ rd,      // [N,3]
    const float* __restrict__ cw,      // [N,NC]
    const float* __restrict__ ct,      // [N,NC]
    const float* __restrict__ uu_in,   // [N,NF]
    const float* __restrict__ colors,  // [N,NS,3]
    const float* __restrict__ dens,    // [N,NS]
    float* __restrict__ out_rgb,       // [N,3]
    float* __restrict__ out_depth,     // [N]
    float* __restrict__ out_op,        // [N]
    float* __restrict__ out_fp,        // [N,NS,3]
    int nrays)
{
    const int L   = threadIdx.x & 31;
    const int w   = threadIdx.x >> 5;
    const int ray = blockIdx.x * RPB + w;
    if (ray >= nrays) return;          // warp-uniform exit; no block barriers used

    __shared__ float2 sh_cc[RPB][64];   // (cdf[i], ct[i])
    __shared__ int    sh_mk[RPB][160];  // boundary-rank histogram
    __shared__ float  sh_t [RPB][192];  // merged sorted t
    __shared__ float2 sh_tw[RPB][192];  // (t, weight)

    float2* cc  = sh_cc[w];
    int*    mk  = sh_mk[w];
    float*  st  = sh_t[w];
    float2* stw = sh_tw[w];

    // ---- A: global loads (coalesced / vectorized) ----
    const float4 u4 = ((const float4*)(uu_in + (size_t)ray * NF))[L];
    float v0 = u4.x, v1 = u4.y, v2 = u4.z, v3 = u4.w;   // elements 4L..4L+3

    const float2 cw2 = ((const float2*)(cw + (size_t)ray * NC))[L];
    const float2 ct2 = ((const float2*)(ct + (size_t)ray * NC))[L];

    const float ox = ro[3 * ray + 0], oy = ro[3 * ray + 1], oz = ro[3 * ray + 2];
    const float dx = rd[3 * ray + 0], dy = rd[3 * ray + 1], dz = rd[3 * ray + 2];
    const float dnorm = sqrtf(dx * dx + dy * dy + dz * dz);

    // ---- B: cdf build (pair-per-lane warp scan); boundaries stay in regs ----
    float cdf_b1, cdf_b2;               // cdf[2L+1], cdf[2L+2]
    {
        const float a  = cw2.x + 1e-5f;
        const float b  = cw2.y + 1e-5f;
        const float ps = a + b;
        float inc = ps;
        #pragma unroll
        for (int off = 1; off < 32; off <<= 1) {
            float n = __shfl_up_sync(FULLM, inc, off);
            if (L >= off) inc += n;
        }
        const float total = __shfl_sync(FULLM, inc, 31);
        const float invt  = 1.f / total;
        const float excl  = inc - ps;
        const float cdf_e = excl * invt;          // cdf[2L]
        cdf_b1 = (excl + a)  * invt;              // cdf[2L+1]
        cdf_b2 = (excl + ps) * invt;              // cdf[2L+2]
        *(float4*)(cc + 2 * L) = make_float4(cdf_e, ct2.x, cdf_b1, ct2.y);
        *(int4*)(mk + 4 * L) = make_int4(0, 0, 0, 0);
        if (L < 8) *(int4*)(mk + 128 + 4 * L) = make_int4(0, 0, 0, 0);
    }

    // ---- C: bitonic sort of 128 u, 4 elements/thread (e = 4L+i) ----
    #pragma unroll
    for (int k = 2; k <= 128; k <<= 1) {
        #pragma unroll
        for (int j = k >> 1; j >= 4; j >>= 1) {
            const bool up = ((L & (k >> 2)) == 0);   // k>=8 here
            const bool lw = ((L & (j >> 2)) == 0);
            const bool km = (up == lw);
            float w0 = __shfl_xor_sync(FULLM, v0, j >> 2);
            float w1 = __shfl_xor_sync(FULLM, v1, j >> 2);
            float w2 = __shfl_xor_sync(FULLM, v2, j >> 2);
            float w3 = __shfl_xor_sync(FULLM, v3, j >> 2);
            v0 = km ? fminf(v0, w0) : fmaxf(v0, w0);
            v1 = km ? fminf(v1, w1) : fmaxf(v1, w1);
            v2 = km ? fminf(v2, w2) : fmaxf(v2, w2);
            v3 = km ? fminf(v3, w3) : fmaxf(v3, w3);
        }
        if (k >= 4) {  // j = 2 : pairs (v0,v2), (v1,v3)
            const bool up = (k == 4) ? ((L & 1) == 0) : ((L & (k >> 2)) == 0);
            CEPAIR(v0, v2, up); CEPAIR(v1, v3, up);
        }
        // j = 1 : pairs (v0,v1), (v2,v3)
        if (k == 2) {
            CEPAIR(v0, v1, true);  CEPAIR(v2, v3, false);
        } else {
            const bool up = (k == 4) ? ((L & 1) == 0) : ((L & (k >> 2)) == 0);
            CEPAIR(v0, v1, up);    CEPAIR(v2, v3, up);
        }
    }
    __syncwarp();

    // ---- D1: boundary ranks via REGISTER search (no shared su at all) ----
    {
        const float m = v3;  // lane max of sorted quad; ascending across lanes
        auto rank128r = [&](float c) -> int {
            float pv; int r = 0;
            pv = __shfl_sync(FULLM, m, 15);     if (pv < c) r = 16;
            pv = __shfl_sync(FULLM, m, r + 7);  if (pv < c) r += 8;
            pv = __shfl_sync(FULLM, m, r + 3);  if (pv < c) r += 4;
            pv = __shfl_sync(FULLM, m, r + 1);  if (pv < c) r += 2;
            pv = __shfl_sync(FULLM, m, r);      if (pv < c) r += 1;     // r<=30 here
            pv = __shfl_sync(FULLM, m, 31);     if (r == 31 && pv < c) r = 32;
            const int rl = (r < 32) ? r : 31;
            const float a0 = __shfl_sync(FULLM, v0, rl);
            const float a1 = __shfl_sync(FULLM, v1, rl);
            const float a2 = __shfl_sync(FULLM, v2, rl);
            int rank = 4 * r;                   // r==32 -> 128
            if (r < 32) rank += (a0 < c) + (a1 < c) + (a2 < c);
            return rank;
        };
        const int s1 = rank128r(cdf_b1);
        const int s2 = rank128r(cdf_b2);
        atomicAdd(&mk[s1], 1);
        atomicAdd(&mk[s2], 1);
        int r0 = __shfl_up_sync(FULLM, s2, 1);
        if (L == 0) r0 = 0;
        st[2 * L + r0]     = ct2.x;
        st[2 * L + 1 + s1] = ct2.y;
    }
    __syncwarp();

    // ---- D2: lo via prefix of histogram; interpolate + scatter fine ----
    {
        const int4 m4 = *(const int4*)(mk + 4 * L);
        const int c0 = m4.x;
        const int c1 = c0 + m4.y;
        const int c2 = c1 + m4.z;
        const int c3 = c2 + m4.w;
        int inc = c3;
        #pragma unroll
        for (int off = 1; off < 32; off <<= 1) {
            int n = __shfl_up_sync(FULLM, inc, off);
            if (L >= off) inc += n;
        }
        const int exc = inc - c3;
        const int lov[4] = {1 + exc + c0, 1 + exc + c1, 1 + exc + c2, 1 + exc + c3};
        const float va[4] = {v0, v1, v2, v3};
        #pragma unroll
        for (int i = 0; i < 4; i++) {
            const int   lo = lov[i];
            const float uu = va[i];
            const int below = min(lo - 1, NC - 1);
            const int above = min(lo,     NC - 1);
            const float2 ccb = cc[below];
            const float2 cca = cc[above];
            float denom = cca.x - ccb.x;
            if (denom < 1e-5f) denom = 1.f;
            const float tt = (uu - ccb.x) / denom;
            const float fv = ccb.y + tt * (cca.y - ccb.y);
            st[4 * L + i + min(lo, NC)] = fv;
        }
    }
    __syncwarp();

    // ---- F: alpha + transmittance (thread owns samples 6L..6L+5) ----
    float dep = 0.f, op = 0.f;
    {
        const float2 tA = *(const float2*)(st + 6 * L);
        const float2 tB = *(const float2*)(st + 6 * L + 2);
        const float2 tC = *(const float2*)(st + 6 * L + 4);
        const float tb[6] = {tA.x, tA.y, tB.x, tB.y, tC.x, tC.y};
        const float t6 = (L < 31) ? st[6 * L + 6] : 0.f;

        const float* dvp = dens + (size_t)ray * NS + 6 * L;
        const float2 dva = *(const float2*)(dvp + 0);
        const float2 dvb = *(const float2*)(dvp + 2);
        const float2 dvc = *(const float2*)(dvp + 4);
        const float dvv[6] = {dva.x, dva.y, dvb.x, dvb.y, dvc.x, dvc.y};

        float alpha[6];
        float run = 1.f;
        #pragma unroll
        for (int i = 0; i < 6; i++) {
            float dist;
            if (i < 5)          dist = tb[i + 1] - tb[i];
            else if (L == 31)   dist = 1e10f;
            else                dist = t6 - tb[5];
            dist *= dnorm;
            alpha[i] = 1.f - __expf(-dvv[i] * dist);
            run *= (1.f - alpha[i] + 1e-10f);
        }
        float inc = run;
        #pragma unroll
        for (int off = 1; off < 32; off <<= 1) {
            float n = __shfl_up_sync(FULLM, inc, off);
            if (L >= off) inc *= n;
        }
        float wex = __shfl_up_sync(FULLM, inc, 1);
        if (L == 0) wex = 1.f;

        float run2 = wex;                 // running transmittance
        #pragma unroll
        for (int i = 0; i < 6; i++) {
            const float wt = alpha[i] * run2;
            stw[6 * L + i] = make_float2(tb[i], wt);
            dep += wt * tb[i];
            op  += wt;
            run2 *= (1.f - alpha[i] + 1e-10f);
        }
    }
    __syncwarp();

    // ---- G: float4 fp stores + rgb accumulation (contiguous stw reads) ----
    float A0 = 0.f, A1 = 0.f, A2 = 0.f;
    const int rB = L % 3;
    {
        const float oR0 = (rB == 0) ? ox : ((rB == 1) ? oy : oz);
        const float oR1 = (rB == 0) ? oy : ((rB == 1) ? oz : ox);
        const float oR2 = (rB == 0) ? oz : ((rB == 1) ? ox : oy);
        const float dR0 = (rB == 0) ? dx : ((rB == 1) ? dy : dz);
        const float dR1 = (rB == 0) ? dy : ((rB == 1) ? dz : dx);
        const float dR2 = (rB == 0) ? dz : ((rB == 1) ? dx : dy);
        float* fpb = out_fp + (size_t)ray * (NS * 3);
        const float4* c4 = (const float4*)(colors + (size_t)ray * (NS * 3));

        #pragma unroll
        for (int h = 0; h < 4; h++) {
            const float4 cvi = __ldg(&c4[32 * h + L]);
            const int e0  = 128 * h + 4 * L;
            const int sa  = e0 / 3;
            const int r0  = e0 - 3 * sa;           // e0 % 3
            const float2 twa = stw[sa];
            const float2 twb = stw[sa + 1];
            // float j uses sample sa+1 iff r0 + j >= 3
            const float t0 = twa.x;
            const float w0 = twa.y;
            const float t1 = (r0 == 2) ? twb.x : twa.x;
            const float w1 = (r0 == 2) ? twb.y : twa.y;
            const float t2 = (r0 >= 1) ? twb.x : twa.x;
            const float w2 = (r0 >= 1) ? twb.y : twa.y;
            const float t3 = twb.x;
            const float w3 = twb.y;
            // channel slot q_j = (2h + j) % 3 (compile-time)
            const int q0 = (2 * h + 0) % 3, q1 = (2 * h + 1) % 3;
            const int q2 = (2 * h + 2) % 3, q3 = (2 * h + 3) % 3;
            const float oA = (q0 == 0) ? oR0 : ((q0 == 1) ? oR1 : oR2);
            const float dA = (q0 == 0) ? dR0 : ((q0 == 1) ? dR1 : dR2);
            const float oB = (q1 == 0) ? oR0 : ((q1 == 1) ? oR1 : oR2);
            const float dB = (q1 == 0) ? dR0 : ((q1 == 1) ? dR1 : dR2);
            const float oC = (q2 == 0) ? oR0 : ((q2 == 1) ? oR1 : oR2);
            const float dC = (q2 == 0) ? dR0 : ((q2 == 1) ? dR1 : dR2);
            const float oD = (q3 == 0) ? oR0 : ((q3 == 1) ? oR1 : oR2);
            const float dD = (q3 == 0) ? dR0 : ((q3 == 1) ? dR1 : dR2);
            *(float4*)(fpb + e0) = make_float4(oA + dA * t0, oB + dB * t1,
                                               oC + dC * t2, oD + dD * t3);
            const float g0 = w0 * cvi.x, g1 = w1 * cvi.y;
            const float g2 = w2 * cvi.z, g3 = w3 * cvi.w;
            if (q0 == 0) A0 += g0; else if (q0 == 1) A1 += g0; else A2 += g0;
            if (q1 == 0) A0 += g1; else if (q1 == 1) A1 += g1; else A2 += g1;
            if (q2 == 0) A0 += g2; else if (q2 == 1) A1 += g2; else A2 += g2;
            if (q3 == 0) A0 += g3; else if (q3 == 1) A1 += g3; else A2 += g3;
        }

        // tail: elements 512 + 2L, 512 + 2L + 1 (float2)
        {
            const float2* c2p = (const float2*)(colors + (size_t)ray * (NS * 3) + 512);
            const float2 cvi = __ldg(&c2p[L]);
            const int e0 = 512 + 2 * L;
            const int s0 = e0 / 3;
            const int s1 = (e0 + 1) / 3;
            const float2 tw0 = stw[s0];
            const float2 tw1 = stw[s1];
            const int qt0 = (2 + rB) % 3;
            const int qt1 = rB;
            const float o0 = (qt0 == 0) ? oR0 : ((qt0 == 1) ? oR1 : oR2);
            const float d0 = (qt0 == 0) ? dR0 : ((qt0 == 1) ? dR1 : dR2);
            const float o1 = (qt1 == 0) ? oR0 : ((qt1 == 1) ? oR1 : oR2);
            const float d1 = (qt1 == 0) ? dR0 : ((qt1 == 1) ? dR1 : dR2);
            *(float2*)(fpb + e0) = make_float2(o0 + d0 * tw0.x, o1 + d1 * tw1.x);
            const float g0 = tw0.y * cvi.x;
            const float g1 = tw1.y * cvi.y;
            if (qt0 == 0) A0 += g0; else if (qt0 == 1) A1 += g0; else A2 += g0;
            if (qt1 == 0) A0 += g1; else if (qt1 == 1) A1 += g1; else A2 += g1;
        }
    }

    // ---- H: final reductions (single warp, no shared) ----
    {
        // channel c lives in A[(c - rB) mod 3] == A[(c + 2L) % 3]
        const int i0 = (2 * L) % 3, i1 = (2 * L + 1) % 3, i2 = (2 * L + 2) % 3;
        float rC = (i0 == 0) ? A0 : ((i0 == 1) ? A1 : A2);
        float gC = (i1 == 0) ? A0 : ((i1 == 1) ? A1 : A2);
        float bC = (i2 == 0) ? A0 : ((i2 == 1) ? A1 : A2);
        #pragma unroll
        for (int off = 16; off; off >>= 1) {
            rC  += __shfl_xor_sync(FULLM, rC,  off);
            gC  += __shfl_xor_sync(FULLM, gC,  off);
            bC  += __shfl_xor_sync(FULLM, bC,  off);
            dep += __shfl_xor_sync(FULLM, dep, off);
            op  += __shfl_xor_sync(FULLM, op,  off);
        }
        if (L == 0) {
            out_rgb[3 * ray + 0] = rC;
            out_rgb[3 * ray + 1] = gC;
            out_rgb[3 * ray + 2] = bC;
            out_depth[ray] = dep;
            out_op[ray]    = op;
        }
    }
}

extern "C" void kernel_launch(void* const* d_in, const int* in_sizes, int n_in,
                              void* d_out, int out_size)
{
    const float* ro     = (const float*)d_in[0];
    const float* rd     = (const float*)d_in[1];
    const float* cw     = (const float*)d_in[2];
    const float* ct     = (const float*)d_in[3];
    const float* u      = (const float*)d_in[4];
    const float* colors = (const float*)d_in[5];
    const float* dens   = (const float*)d_in[6];

    const int N = in_sizes[0] / 3;

    float* out       = (float*)d_out;
    float* out_rgb   = out;                 // [N,3]
    float* out_depth = out + (size_t)N * 3; // [N]
    float* out_op    = out_depth + N;       // [N]
    float* out_fp    = out_op + N;          // [N,NS,3]

    const int blocks = (N + RPB - 1) / RPB;
    gridnerf_kernel<<<blocks, 32 * RPB>>>(ro, rd, cw, ct, u, colors, dens,
                                          out_rgb, out_depth, out_op, out_fp, N);
}